// round 15
// baseline (speedup 1.0000x reference)
#include <cuda_runtime.h>
#include <cuda_fp16.h>
#include <math.h>

// ---------------------------------------------------------------------------
// Problem constants (fixed by dataset; runtime sizes still read from in_sizes)
// ---------------------------------------------------------------------------
#define D_C       128
#define MAX_ITEMS 200000
#define MAX_USERS 100000
#define MAX_EII   3200000
#define MAX_EUI   1600000
#define MAX_EDGES (3 * MAX_EII + MAX_EUI)          // 11.2M
#define MAX_ROWS  (3 * MAX_ITEMS + MAX_USERS)      // 700K logical output rows
#define SCAN_CHUNK 4096
#define MAX_PARTS ((MAX_ROWS + SCAN_CHUNK - 1) / SCAN_CHUNK + 1)

// smem byte layout for score kernel (padded pitches -> conflict-free frags)
#define IPITCH 544            // 64 pair-rows x (128 half2 = 512B data + 32B pad)
#define ZPITCH 272            // 64 rows x (128 half = 256B data + 16B pad)
#define SM_I   0
#define SM_Z   (64 * IPITCH)                 // 34816
#define SM_S2  (SM_Z + 64 * ZPITCH)          // 52224
#define SM_S   (SM_S2 + 2 * 64 * 4)          // 52736
#define SM_TOT (SM_S + 3 * 64 * 4)           // 53504

// Static device scratch (no allocs allowed).
__device__ __half2 g_nbh [(size_t)3 * MAX_ITEMS * D_C / 2]; // fp16 nb aggregates
__device__ __half2 g_xh  [(size_t)MAX_ITEMS * D_C / 2];     // fp16 copy of x
__device__ __half2 g_Ih  [3 * D_C * D_C / 2];               // fp16 copies of I0..2
__device__ int2    g_bpk [MAX_EDGES];                       // binned (src, val-bits)
__device__ int     g_cnt [MAX_ROWS];
__device__ int     g_off [MAX_ROWS + 1];
__device__ int     g_cur [MAX_ROWS];
__device__ int     g_part[MAX_PARTS];

// ---------------------------------------------------------------------------
// Pass 0a: convert x to fp16
// ---------------------------------------------------------------------------
__global__ void x2h_kernel(const float4* __restrict__ x4,
                           __half2* __restrict__ xh, int n4)
{
    int i = blockIdx.x * blockDim.x + threadIdx.x;
    if (i < n4) {
        float4 v = x4[i];
        xh[2 * i]     = __floats2half2_rn(v.x, v.y);
        xh[2 * i + 1] = __floats2half2_rn(v.z, v.w);
    }
}

// Pass 0b: convert the three I matrices to fp16 (row-major, half2 in n)
__global__ void i2h_kernel(const float2* __restrict__ I0,
                           const float2* __restrict__ I1,
                           const float2* __restrict__ I2,
                           __half2* __restrict__ Ih)
{
    int i = blockIdx.x * blockDim.x + threadIdx.x;   // over 3 * 8192 half2
    if (i < 3 * D_C * D_C / 2) {
        int rel = i / (D_C * D_C / 2);
        int j   = i % (D_C * D_C / 2);
        const float2* Ip = (rel == 0) ? I0 : (rel == 1) ? I1 : I2;
        float2 v = Ip[j];
        Ih[i] = __floats2half2_rn(v.x, v.y);
    }
}

// ---------------------------------------------------------------------------
// Pass 1: histogram of destination rows (unchanged — DVFS clock canary)
// ---------------------------------------------------------------------------
__global__ void hist_kernel(const int* __restrict__ dst, int nE, int base,
                            int* __restrict__ cnt)
{
    int i0 = (blockIdx.x * blockDim.x + threadIdx.x) * 4;
    if (i0 + 3 < nE) {
        int4 d = *reinterpret_cast<const int4*>(dst + i0);
        atomicAdd(&cnt[base + d.x], 1);
        atomicAdd(&cnt[base + d.y], 1);
        atomicAdd(&cnt[base + d.z], 1);
        atomicAdd(&cnt[base + d.w], 1);
    } else {
        for (int j = i0; j < nE; j++) atomicAdd(&cnt[base + dst[j]], 1);
    }
}

// ---------------------------------------------------------------------------
// Pass 2a/2b/2c: parallel exclusive scan (unchanged)
// ---------------------------------------------------------------------------
__global__ void __launch_bounds__(1024)
block_sum_kernel(const int* __restrict__ cnt, int* __restrict__ part, int N)
{
    __shared__ int ws[32];
    const int tid = threadIdx.x, lane = tid & 31, wid = tid >> 5;
    int idx = blockIdx.x * SCAN_CHUNK + tid * 4;
    int t = 0;
    if (idx + 3 < N) {
        int4 v = *reinterpret_cast<const int4*>(cnt + idx);
        t = v.x + v.y + v.z + v.w;
    } else {
        for (int j = idx; j < min(idx + 4, N); j++) t += cnt[j];
    }
#pragma unroll
    for (int o = 16; o > 0; o >>= 1) t += __shfl_xor_sync(0xffffffffu, t, o);
    if (lane == 0) ws[wid] = t;
    __syncthreads();
    if (wid == 0) {
        int u = ws[lane];
#pragma unroll
        for (int o = 16; o > 0; o >>= 1) u += __shfl_xor_sync(0xffffffffu, u, o);
        if (lane == 0) part[blockIdx.x] = u;
    }
}

__global__ void __launch_bounds__(1024)
part_scan_kernel(int* __restrict__ part, int nparts, int* __restrict__ off_total)
{
    __shared__ int wtot[32];
    const int tid = threadIdx.x, lane = tid & 31, wid = tid >> 5;
    int v = (tid < nparts) ? part[tid] : 0;
    int incl = v;
#pragma unroll
    for (int o = 1; o < 32; o <<= 1) {
        int u = __shfl_up_sync(0xffffffffu, incl, o);
        if (lane >= o) incl += u;
    }
    if (lane == 31) wtot[wid] = incl;
    __syncthreads();
    if (wid == 0) {
        int w = wtot[lane];
        int wi = w;
#pragma unroll
        for (int o = 1; o < 32; o <<= 1) {
            int u = __shfl_up_sync(0xffffffffu, wi, o);
            if (lane >= o) wi += u;
        }
        wtot[lane] = wi - w;
    }
    __syncthreads();
    int excl = wtot[wid] + incl - v;
    if (tid < nparts) part[tid] = excl;
    if (tid == nparts - 1) *off_total = excl + v;
}

__global__ void __launch_bounds__(1024)
scan_final_kernel(const int* __restrict__ cnt, const int* __restrict__ part,
                  int* __restrict__ off, int* __restrict__ cur, int N)
{
    __shared__ int wtot[32];
    __shared__ int wexcl[32];
    const int tid = threadIdx.x, lane = tid & 31, wid = tid >> 5;
    int idx = blockIdx.x * SCAN_CHUNK + tid * 4;

    int4 v = make_int4(0, 0, 0, 0);
    if (idx + 3 < N)      v = *reinterpret_cast<const int4*>(cnt + idx);
    else if (idx < N) {
        v.x = cnt[idx];
        if (idx + 1 < N) v.y = cnt[idx + 1];
        if (idx + 2 < N) v.z = cnt[idx + 2];
    }
    int t0 = v.x, t1 = t0 + v.y, t2 = t1 + v.z, t3 = t2 + v.w;

    int incl = t3;
#pragma unroll
    for (int o = 1; o < 32; o <<= 1) {
        int u = __shfl_up_sync(0xffffffffu, incl, o);
        if (lane >= o) incl += u;
    }
    int thr_excl = incl - t3;
    if (lane == 31) wtot[wid] = incl;
    __syncthreads();
    if (wid == 0) {
        int w = wtot[lane];
        int wi = w;
#pragma unroll
        for (int o = 1; o < 32; o <<= 1) {
            int u = __shfl_up_sync(0xffffffffu, wi, o);
            if (lane >= o) wi += u;
        }
        wexcl[lane] = wi - w;
    }
    __syncthreads();
    int ex = part[blockIdx.x] + wexcl[wid] + thr_excl;
    if (idx + 3 < N) {
        int4 o4 = make_int4(ex, ex + t0, ex + t1, ex + t2);
        *reinterpret_cast<int4*>(off + idx) = o4;
        *reinterpret_cast<int4*>(cur + idx) = o4;
    } else if (idx < N) {
        off[idx] = ex;           cur[idx] = ex;
        if (idx + 1 < N) { off[idx + 1] = ex + t0; cur[idx + 1] = ex + t0; }
        if (idx + 2 < N) { off[idx + 2] = ex + t1; cur[idx + 2] = ex + t1; }
    }
}

// ---------------------------------------------------------------------------
// Pass 3: merged scatter — ONE launch, blockIdx.y selects the relation.
// One packed 8B write per edge.
// ---------------------------------------------------------------------------
__global__ void scatter4_kernel(
    const int* __restrict__ s0, const int* __restrict__ d0, const float* __restrict__ v0, int n0,
    const int* __restrict__ s1, const int* __restrict__ d1, const float* __restrict__ v1, int n1,
    const int* __restrict__ s2, const int* __restrict__ d2, const float* __restrict__ v2, int n2,
    const int* __restrict__ s3, const int* __restrict__ d3, const float* __restrict__ v3, int n3e,
    int ni, int* __restrict__ cur, int2* __restrict__ bpk)
{
    int rel = blockIdx.y;
    const int*   src; const int* dst; const float* val; int nE; int base;
    if      (rel == 0) { src = s0; dst = d0; val = v0; nE = n0;  base = 0;      }
    else if (rel == 1) { src = s1; dst = d1; val = v1; nE = n1;  base = ni;     }
    else if (rel == 2) { src = s2; dst = d2; val = v2; nE = n2;  base = 2 * ni; }
    else               { src = s3; dst = d3; val = v3; nE = n3e; base = 3 * ni; }

    int i = blockIdx.x * blockDim.x + threadIdx.x;
    if (i < nE) {
        int d   = dst[i];
        int pos = atomicAdd(&cur[base + d], 1);
        bpk[pos] = make_int2(src[i], __float_as_int(val[i]));
    }
}

// ---------------------------------------------------------------------------
// Pass 4: gather-accumulate from fp16 x, MLP=4 (u64 loads are cheap in regs).
// One warp per output row; each lane owns 4 columns (8B per edge).
// fp32 accumulation; items -> fp16 nbh, users -> fp32 u_emb.
// ---------------------------------------------------------------------------
__global__ void __launch_bounds__(256)
gather_kernel(const int* __restrict__ off,
              const int2* __restrict__ bpk,
              const __half2* __restrict__ xh,
              __half2* __restrict__ nbh, float* __restrict__ uemb,
              int n3, int nrows)
{
    int w = (blockIdx.x * blockDim.x + threadIdx.x) >> 5;
    if (w >= nrows) return;
    const int lane = threadIdx.x & 31;

    unsigned long long pol;
    asm("createpolicy.fractional.L2::evict_last.b64 %0, 1.0;" : "=l"(pol));

    int beg = __ldg(off + w);
    int end = __ldg(off + w + 1);

    float4 a0 = make_float4(0.f, 0.f, 0.f, 0.f);
    float4 a1 = make_float4(0.f, 0.f, 0.f, 0.f);
    float4 a2 = make_float4(0.f, 0.f, 0.f, 0.f);
    float4 a3 = make_float4(0.f, 0.f, 0.f, 0.f);

#define XLOADH(D, SRC)                                                         \
    {                                                                          \
        const __half2* xp = xh + (size_t)(SRC) * (D_C / 2) + lane * 2;         \
        asm volatile("ld.global.nc.L2::cache_hint.b64 %0, [%1], %2;"           \
                     : "=l"(D) : "l"(xp), "l"(pol));                           \
    }
#define XFMAH(A, D, V)                                                         \
    {                                                                          \
        unsigned int _lo = (unsigned int)(D);                                  \
        unsigned int _hi = (unsigned int)((D) >> 32);                          \
        float2 _f0 = __half22float2(*reinterpret_cast<__half2*>(&_lo));        \
        float2 _f1 = __half22float2(*reinterpret_cast<__half2*>(&_hi));        \
        A.x = fmaf(_f0.x, V, A.x); A.y = fmaf(_f0.y, V, A.y);                  \
        A.z = fmaf(_f1.x, V, A.z); A.w = fmaf(_f1.y, V, A.w);                  \
    }

    for (int p = beg; p < end; p += 32) {
        int n = min(32, end - p);
        int2 pk = make_int2(0, 0);
        if (lane < n) pk = __ldg(bpk + p + lane);

        int e = 0;
        for (; e + 4 <= n; e += 4) {
            int   s0 = __shfl_sync(0xffffffffu, pk.x, e);
            int   s1 = __shfl_sync(0xffffffffu, pk.x, e + 1);
            int   s2 = __shfl_sync(0xffffffffu, pk.x, e + 2);
            int   s3 = __shfl_sync(0xffffffffu, pk.x, e + 3);
            float v0 = __int_as_float(__shfl_sync(0xffffffffu, pk.y, e));
            float v1 = __int_as_float(__shfl_sync(0xffffffffu, pk.y, e + 1));
            float v2 = __int_as_float(__shfl_sync(0xffffffffu, pk.y, e + 2));
            float v3 = __int_as_float(__shfl_sync(0xffffffffu, pk.y, e + 3));
            unsigned long long d0, d1, d2, d3;
            XLOADH(d0, s0); XLOADH(d1, s1); XLOADH(d2, s2); XLOADH(d3, s3);
            XFMAH(a0, d0, v0); XFMAH(a1, d1, v1);
            XFMAH(a2, d2, v2); XFMAH(a3, d3, v3);
        }
        for (; e < n; e++) {
            int   se = __shfl_sync(0xffffffffu, pk.x, e);
            float ve = __int_as_float(__shfl_sync(0xffffffffu, pk.y, e));
            unsigned long long d; XLOADH(d, se); XFMAH(a0, d, ve);
        }
    }
#undef XLOADH
#undef XFMAH

    a0.x += a1.x + a2.x + a3.x;
    a0.y += a1.y + a2.y + a3.y;
    a0.z += a1.z + a2.z + a3.z;
    a0.w += a1.w + a2.w + a3.w;

    if (w < n3) {
        __half2 h0 = __floats2half2_rn(a0.x, a0.y);
        __half2 h1 = __floats2half2_rn(a0.z, a0.w);
        unsigned long long dv =
            ((unsigned long long)*reinterpret_cast<unsigned int*>(&h1) << 32) |
            *reinterpret_cast<unsigned int*>(&h0);
        *reinterpret_cast<unsigned long long*>(
            nbh + (size_t)w * (D_C / 2) + lane * 2) = dv;
    } else {
        *reinterpret_cast<float4*>(
            uemb + (size_t)(w - n3) * D_C + lane * 4) = a0;
    }
}

// ---------------------------------------------------------------------------
// Score + combine v4.1 (UNCHANGED from round 14 — it won big; protect it):
// HMMA tensor-core matvec, 8 warps, 64 rows/block.
// ---------------------------------------------------------------------------
__device__ __forceinline__ float4 h4_to_f4(unsigned long long d)
{
    unsigned int lo = (unsigned int)d;
    unsigned int hi = (unsigned int)(d >> 32);
    float2 f0 = __half22float2(*reinterpret_cast<__half2*>(&lo));
    float2 f1 = __half22float2(*reinterpret_cast<__half2*>(&hi));
    return make_float4(f0.x, f0.y, f1.x, f1.y);
}

__device__ __forceinline__ float leaky(float h)
{
    return (h >= 0.f) ? h : 0.2f * h;
}

__global__ void __launch_bounds__(256, 2)
score_kernel(const __half2* __restrict__ xh,
             const __half2* __restrict__ nbh,
             const __half2* __restrict__ Ih,   // 3 x 128 x 128 fp16 row-major
             float* __restrict__ out,
             int nrows)
{
    extern __shared__ char smc[];
    char*  I_b  = smc + SM_I;    // pair rows: I_pair[p][n] = (I[2p][n], I[2p+1][n])
    char*  Z_b  = smc + SM_Z;    // Z[r][k] fp16, ZPITCH bytes per row
    float* s2   = reinterpret_cast<float*>(smc + SM_S2);  // [2][64]
    float* s_sh = reinterpret_cast<float*>(smc + SM_S);   // [3][64]

    const int tid  = threadIdx.x;
    const int lane = tid & 31;
    const int wid  = tid >> 5;          // 8 warps
    const int gid  = lane >> 2;         // 0..7
    const int m    = lane & 3;          // 0..3
    const int rt   = wid >> 1;          // row tile 0..3 (16 rows each)
    const int ch   = wid & 1;           // col half 0..1 (64 cols each)
    const int row0 = blockIdx.x * 64;
    const int rows = min(64, nrows - row0);
    const size_t rel_stride = (size_t)nrows * (D_C / 2);  // half2 units

#pragma unroll 1
    for (int rel = 0; rel < 3; rel++) {
        const __half2* nbp  = nbh + (size_t)rel * rel_stride;
        const unsigned int* Ig =
            reinterpret_cast<const unsigned int*>(Ih + (size_t)rel * (D_C * D_C / 2));

        // ---- stage I as k-pair-interleaved half2 rows (ALL 64 n-pairs) -------
        for (int idx = tid; idx < 64 * 64; idx += 256) {
            int p = idx >> 6;          // k-pair row 0..63
            int j = idx & 63;          // n-pair 0..63 (n = 2j, 2j+1)
            unsigned int u0 = Ig[(2 * p)     * 64 + j];
            unsigned int u1 = Ig[(2 * p + 1) * 64 + j];
            __half2 h0 = *reinterpret_cast<__half2*>(&u0);
            __half2 h1 = *reinterpret_cast<__half2*>(&u1);
            __half2 lo = __lows2half2(h0, h1);
            __half2 hi = __highs2half2(h0, h1);
            unsigned long long dv =
                ((unsigned long long)*reinterpret_cast<unsigned int*>(&hi) << 32) |
                *reinterpret_cast<unsigned int*>(&lo);
            *reinterpret_cast<unsigned long long*>(I_b + p * IPITCH + j * 8) = dv;
        }
        // ---- stage Z = xh * nbh (fp16) ---------------------------------------
        for (int idx = tid; idx < 64 * 32; idx += 256) {
            int r = idx >> 5;
            int q = idx & 31;          // 4-half group
            unsigned long long dz = 0ull;
            if (r < rows) {
                size_t offh = (size_t)(row0 + r) * (D_C / 2) + (q << 1);
                unsigned long long dx =
                    *reinterpret_cast<const unsigned long long*>(xh + offh);
                unsigned long long dn =
                    *reinterpret_cast<const unsigned long long*>(nbp + offh);
                unsigned int xl = (unsigned int)dx, xu = (unsigned int)(dx >> 32);
                unsigned int nl = (unsigned int)dn, nu = (unsigned int)(dn >> 32);
                __half2 zl = __hmul2(*reinterpret_cast<__half2*>(&xl),
                                     *reinterpret_cast<__half2*>(&nl));
                __half2 zu = __hmul2(*reinterpret_cast<__half2*>(&xu),
                                     *reinterpret_cast<__half2*>(&nu));
                dz = ((unsigned long long)*reinterpret_cast<unsigned int*>(&zu) << 32) |
                     *reinterpret_cast<unsigned int*>(&zl);
            }
            *reinterpret_cast<unsigned long long*>(Z_b + r * ZPITCH + q * 8) = dz;
        }
        __syncthreads();

        // ---- HMMA: 8 k-steps x 8 n-tiles --------------------------------------
        float acc[8][4];
#pragma unroll
        for (int ct = 0; ct < 8; ct++)
#pragma unroll
            for (int c = 0; c < 4; c++) acc[ct][c] = 0.f;

        const char* za = Z_b + (rt * 16 + gid) * ZPITCH + m * 4;
#pragma unroll
        for (int ks = 0; ks < 8; ks++) {
            const char* zk = za + ks * 32;
            unsigned int fa0 = *reinterpret_cast<const unsigned int*>(zk);
            unsigned int fa1 = *reinterpret_cast<const unsigned int*>(zk + 8 * ZPITCH);
            unsigned int fa2 = *reinterpret_cast<const unsigned int*>(zk + 16);
            unsigned int fa3 = *reinterpret_cast<const unsigned int*>(zk + 8 * ZPITCH + 16);
            const char* ik = I_b + (8 * ks + m) * IPITCH + (ch * 64 + gid) * 4;
#pragma unroll
            for (int ct = 0; ct < 8; ct++) {
                unsigned int fb0 = *reinterpret_cast<const unsigned int*>(ik + ct * 32);
                unsigned int fb1 = *reinterpret_cast<const unsigned int*>(ik + ct * 32 + 4 * IPITCH);
                asm volatile(
                    "mma.sync.aligned.m16n8k16.row.col.f32.f16.f16.f32 "
                    "{%0,%1,%2,%3}, {%4,%5,%6,%7}, {%8,%9}, {%0,%1,%2,%3};"
                    : "+f"(acc[ct][0]), "+f"(acc[ct][1]),
                      "+f"(acc[ct][2]), "+f"(acc[ct][3])
                    : "r"(fa0), "r"(fa1), "r"(fa2), "r"(fa3),
                      "r"(fb0), "r"(fb1));
            }
        }

        // ---- leaky + column-sum + cross-lane reduce ---------------------------
        float rs0 = 0.f, rs1 = 0.f;
#pragma unroll
        for (int ct = 0; ct < 8; ct++) {
            rs0 += leaky(acc[ct][0]) + leaky(acc[ct][1]);   // row rt*16+gid
            rs1 += leaky(acc[ct][2]) + leaky(acc[ct][3]);   // row rt*16+gid+8
        }
        rs0 += __shfl_xor_sync(0xffffffffu, rs0, 1);
        rs0 += __shfl_xor_sync(0xffffffffu, rs0, 2);
        rs1 += __shfl_xor_sync(0xffffffffu, rs1, 1);
        rs1 += __shfl_xor_sync(0xffffffffu, rs1, 2);
        if (m == 0) {
            s2[ch * 64 + rt * 16 + gid]     = rs0;
            s2[ch * 64 + rt * 16 + gid + 8] = rs1;
        }
        __syncthreads();
        if (tid < 64)
            s_sh[rel * 64 + tid] =
                (s2[tid] + s2[64 + tid]) * 0.08838834764831845f;   // 1/sqrt(128)
    }
    __syncthreads();

    // ---- softmax over relations + weighted combine (fp16 nb, fp32 out) -------
    float4* og = reinterpret_cast<float4*>(out);
    for (int idx = tid; idx < 64 * 32; idx += 256) {
        int r  = idx >> 5;
        int c4 = idx & 31;
        if (r >= rows) continue;
        float s0 = s_sh[r];
        float s1 = s_sh[64 + r];
        float s2v = s_sh[128 + r];
        float mx = fmaxf(s0, fmaxf(s1, s2v));
        float e0 = __expf(s0 - mx);
        float e1 = __expf(s1 - mx);
        float e2 = __expf(s2v - mx);
        float inv = 1.f / (e0 + e1 + e2);
        float w0 = e0 * inv, w1 = e1 * inv, w2 = e2 * inv;

        size_t offh = (size_t)(row0 + r) * (D_C / 2) + (c4 << 1);
        float4 av = h4_to_f4(*reinterpret_cast<const unsigned long long*>(nbh + offh));
        float4 bv = h4_to_f4(*reinterpret_cast<const unsigned long long*>(nbh + rel_stride + offh));
        float4 cv = h4_to_f4(*reinterpret_cast<const unsigned long long*>(nbh + 2 * rel_stride + offh));
        float4 o;
        o.x = w0 * av.x + w1 * bv.x + w2 * cv.x;
        o.y = w0 * av.y + w1 * bv.y + w2 * cv.y;
        o.z = w0 * av.z + w1 * bv.z + w2 * cv.z;
        o.w = w0 * av.w + w1 * bv.w + w2 * cv.w;
        og[(size_t)(row0 + r) * 32 + c4] = o;
    }
}

// ---------------------------------------------------------------------------
// Launch
// ---------------------------------------------------------------------------
extern "C" void kernel_launch(void* const* d_in, const int* in_sizes, int n_in,
                              void* d_out, int out_size)
{
    int base = (in_sizes[0] == 1) ? 1 : 0;

    const float* x      = (const float*)d_in[base + 0];
    const int*   srcs[4] = { (const int*)d_in[base + 1], (const int*)d_in[base + 4],
                             (const int*)d_in[base + 7], (const int*)d_in[base + 10] };
    const int*   dsts[4] = { (const int*)d_in[base + 2], (const int*)d_in[base + 5],
                             (const int*)d_in[base + 8], (const int*)d_in[base + 11] };
    const float* vals[4] = { (const float*)d_in[base + 3], (const float*)d_in[base + 6],
                             (const float*)d_in[base + 9], (const float*)d_in[base + 12] };
    const float* I0     = (const float*)d_in[base + 13];
    const float* I1     = (const float*)d_in[base + 14];
    const float* I2     = (const float*)d_in[base + 15];

    int n_items = in_sizes[base + 0] / D_C;
    int nE[4]   = { in_sizes[base + 1], in_sizes[base + 4],
                    in_sizes[base + 7], in_sizes[base + 10] };
    int n_users = out_size / D_C - n_items;
    int n3      = 3 * n_items;
    int nrows   = n3 + n_users;

    float* out_f    = (float*)d_out;
    float* u_emb    = out_f;                          // tuple order: (u_emb, neighbor)
    float* neighbor = out_f + (size_t)n_users * D_C;

    __half2 *nbh, *xh, *Ih; int2 *bpk; int *cnt, *off, *cur, *part;
    cudaGetSymbolAddress((void**)&nbh,  g_nbh);
    cudaGetSymbolAddress((void**)&xh,   g_xh);
    cudaGetSymbolAddress((void**)&Ih,   g_Ih);
    cudaGetSymbolAddress((void**)&bpk,  g_bpk);
    cudaGetSymbolAddress((void**)&cnt,  g_cnt);
    cudaGetSymbolAddress((void**)&off,  g_off);
    cudaGetSymbolAddress((void**)&cur,  g_cur);
    cudaGetSymbolAddress((void**)&part, g_part);

    // --- fp16 copies of x and I ------------------------------------------------
    {
        int n4 = n_items * D_C / 4;
        x2h_kernel<<<(n4 + 255) / 256, 256>>>(
            reinterpret_cast<const float4*>(x), xh, n4);
        int ni = 3 * D_C * D_C / 2;
        i2h_kernel<<<(ni + 255) / 256, 256>>>(
            reinterpret_cast<const float2*>(I0),
            reinterpret_cast<const float2*>(I1),
            reinterpret_cast<const float2*>(I2), Ih);
    }

    // --- build CSR bins ----------------------------------------------------------
    cudaMemsetAsync(cnt, 0, (size_t)nrows * sizeof(int), 0);
    for (int r = 0; r < 4; r++) {
        int b = (r < 3) ? r * n_items : n3;
        int g = ((nE[r] + 3) / 4 + 255) / 256;
        hist_kernel<<<g, 256>>>(dsts[r], nE[r], b, cnt);
    }
    int nparts = (nrows + SCAN_CHUNK - 1) / SCAN_CHUNK;
    block_sum_kernel<<<nparts, 1024>>>(cnt, part, nrows);
    part_scan_kernel<<<1, 1024>>>(part, nparts, off + nrows);
    scan_final_kernel<<<nparts, 1024>>>(cnt, part, off, cur, nrows);

    // merged scatter: one launch, y = relation
    {
        int maxE = max(max(nE[0], nE[1]), max(nE[2], nE[3]));
        dim3 grid((maxE + 255) / 256, 4);
        scatter4_kernel<<<grid, 256>>>(
            srcs[0], dsts[0], vals[0], nE[0],
            srcs[1], dsts[1], vals[1], nE[1],
            srcs[2], dsts[2], vals[2], nE[2],
            srcs[3], dsts[3], vals[3], nE[3],
            n_items, cur, bpk);
    }

    // --- gather-accumulate (MLP=4) ------------------------------------------------
    {
        int g = ((nrows * 32) + 255) / 256;
        gather_kernel<<<g, 256>>>(off, bpk, xh, nbh, u_emb, n3, nrows);
    }

    // --- score + combine (tensor-core matvec) --------------------------------------
    cudaFuncSetAttribute(score_kernel,
                         cudaFuncAttributeMaxDynamicSharedMemorySize, SM_TOT);
    int nblocks = (n_items + 63) / 64;
    score_kernel<<<nblocks, 256, SM_TOT>>>(xh, nbh, Ih, neighbor, n_items);
}

// round 16
// speedup vs baseline: 1.0556x; 1.0556x over previous
#include <cuda_runtime.h>
#include <cuda_fp16.h>
#include <math.h>

// ---------------------------------------------------------------------------
// Problem constants (fixed by dataset; runtime sizes still read from in_sizes)
// ---------------------------------------------------------------------------
#define D_C       128
#define MAX_ITEMS 200000
#define MAX_USERS 100000
#define MAX_EII   3200000
#define MAX_EUI   1600000
#define MAX_EDGES (3 * MAX_EII + MAX_EUI)          // 11.2M
#define MAX_ROWS  (3 * MAX_ITEMS + MAX_USERS)      // 700K logical output rows
#define SCAN_CHUNK 4096
#define MAX_PARTS ((MAX_ROWS + SCAN_CHUNK - 1) / SCAN_CHUNK + 1)

// smem byte layout for score kernel (padded pitches -> conflict-free frags)
#define IPITCH 544            // 64 pair-rows x (128 half2 = 512B data + 32B pad)
#define ZPITCH 272            // 64 rows x (128 half = 256B data + 16B pad)
#define SM_I   0
#define SM_Z   (64 * IPITCH)                 // 34816
#define SM_S2  (SM_Z + 64 * ZPITCH)          // 52224
#define SM_S   (SM_S2 + 2 * 64 * 4)          // 52736
#define SM_TOT (SM_S + 3 * 64 * 4)           // 53504

// Static device scratch (no allocs allowed).
__device__ __half2 g_nbh [(size_t)3 * MAX_ITEMS * D_C / 2]; // fp16 nb aggregates
__device__ __half2 g_xh  [(size_t)MAX_ITEMS * D_C / 2];     // fp16 copy of x
__device__ __half2 g_Ih  [3 * D_C * D_C / 2];               // fp16 copies of I0..2
__device__ int2    g_bpk [MAX_EDGES];                       // binned (src, val-bits)
__device__ int     g_cnt [MAX_ROWS];
__device__ int     g_off [MAX_ROWS + 1];
__device__ int     g_cur [MAX_ROWS];
__device__ int     g_part[MAX_PARTS];

// ---------------------------------------------------------------------------
// Pass 0: convert x AND the three I matrices to fp16 in one launch.
// ---------------------------------------------------------------------------
__global__ void conv_kernel(const float4* __restrict__ x4, int n4,
                            const float2* __restrict__ I0,
                            const float2* __restrict__ I1,
                            const float2* __restrict__ I2,
                            __half2* __restrict__ xh,
                            __half2* __restrict__ Ih)
{
    int i = blockIdx.x * blockDim.x + threadIdx.x;
    if (i < n4) {
        float4 v = x4[i];
        xh[2 * i]     = __floats2half2_rn(v.x, v.y);
        xh[2 * i + 1] = __floats2half2_rn(v.z, v.w);
    }
    if (i < 3 * D_C * D_C / 2) {
        int rel = i / (D_C * D_C / 2);
        int j   = i % (D_C * D_C / 2);
        const float2* Ip = (rel == 0) ? I0 : (rel == 1) ? I1 : I2;
        float2 v = Ip[j];
        Ih[i] = __floats2half2_rn(v.x, v.y);
    }
}

// ---------------------------------------------------------------------------
// Pass 1: histogram of destination rows (unchanged — DVFS clock canary)
// ---------------------------------------------------------------------------
__global__ void hist_kernel(const int* __restrict__ dst, int nE, int base,
                            int* __restrict__ cnt)
{
    int i0 = (blockIdx.x * blockDim.x + threadIdx.x) * 4;
    if (i0 + 3 < nE) {
        int4 d = *reinterpret_cast<const int4*>(dst + i0);
        atomicAdd(&cnt[base + d.x], 1);
        atomicAdd(&cnt[base + d.y], 1);
        atomicAdd(&cnt[base + d.z], 1);
        atomicAdd(&cnt[base + d.w], 1);
    } else {
        for (int j = i0; j < nE; j++) atomicAdd(&cnt[base + dst[j]], 1);
    }
}

// ---------------------------------------------------------------------------
// Pass 2a/2b/2c: parallel exclusive scan (unchanged)
// ---------------------------------------------------------------------------
__global__ void __launch_bounds__(1024)
block_sum_kernel(const int* __restrict__ cnt, int* __restrict__ part, int N)
{
    __shared__ int ws[32];
    const int tid = threadIdx.x, lane = tid & 31, wid = tid >> 5;
    int idx = blockIdx.x * SCAN_CHUNK + tid * 4;
    int t = 0;
    if (idx + 3 < N) {
        int4 v = *reinterpret_cast<const int4*>(cnt + idx);
        t = v.x + v.y + v.z + v.w;
    } else {
        for (int j = idx; j < min(idx + 4, N); j++) t += cnt[j];
    }
#pragma unroll
    for (int o = 16; o > 0; o >>= 1) t += __shfl_xor_sync(0xffffffffu, t, o);
    if (lane == 0) ws[wid] = t;
    __syncthreads();
    if (wid == 0) {
        int u = ws[lane];
#pragma unroll
        for (int o = 16; o > 0; o >>= 1) u += __shfl_xor_sync(0xffffffffu, u, o);
        if (lane == 0) part[blockIdx.x] = u;
    }
}

__global__ void __launch_bounds__(1024)
part_scan_kernel(int* __restrict__ part, int nparts, int* __restrict__ off_total)
{
    __shared__ int wtot[32];
    const int tid = threadIdx.x, lane = tid & 31, wid = tid >> 5;
    int v = (tid < nparts) ? part[tid] : 0;
    int incl = v;
#pragma unroll
    for (int o = 1; o < 32; o <<= 1) {
        int u = __shfl_up_sync(0xffffffffu, incl, o);
        if (lane >= o) incl += u;
    }
    if (lane == 31) wtot[wid] = incl;
    __syncthreads();
    if (wid == 0) {
        int w = wtot[lane];
        int wi = w;
#pragma unroll
        for (int o = 1; o < 32; o <<= 1) {
            int u = __shfl_up_sync(0xffffffffu, wi, o);
            if (lane >= o) wi += u;
        }
        wtot[lane] = wi - w;
    }
    __syncthreads();
    int excl = wtot[wid] + incl - v;
    if (tid < nparts) part[tid] = excl;
    if (tid == nparts - 1) *off_total = excl + v;
}

__global__ void __launch_bounds__(1024)
scan_final_kernel(const int* __restrict__ cnt, const int* __restrict__ part,
                  int* __restrict__ off, int* __restrict__ cur, int N)
{
    __shared__ int wtot[32];
    __shared__ int wexcl[32];
    const int tid = threadIdx.x, lane = tid & 31, wid = tid >> 5;
    int idx = blockIdx.x * SCAN_CHUNK + tid * 4;

    int4 v = make_int4(0, 0, 0, 0);
    if (idx + 3 < N)      v = *reinterpret_cast<const int4*>(cnt + idx);
    else if (idx < N) {
        v.x = cnt[idx];
        if (idx + 1 < N) v.y = cnt[idx + 1];
        if (idx + 2 < N) v.z = cnt[idx + 2];
    }
    int t0 = v.x, t1 = t0 + v.y, t2 = t1 + v.z, t3 = t2 + v.w;

    int incl = t3;
#pragma unroll
    for (int o = 1; o < 32; o <<= 1) {
        int u = __shfl_up_sync(0xffffffffu, incl, o);
        if (lane >= o) incl += u;
    }
    int thr_excl = incl - t3;
    if (lane == 31) wtot[wid] = incl;
    __syncthreads();
    if (wid == 0) {
        int w = wtot[lane];
        int wi = w;
#pragma unroll
        for (int o = 1; o < 32; o <<= 1) {
            int u = __shfl_up_sync(0xffffffffu, wi, o);
            if (lane >= o) wi += u;
        }
        wexcl[lane] = wi - w;
    }
    __syncthreads();
    int ex = part[blockIdx.x] + wexcl[wid] + thr_excl;
    if (idx + 3 < N) {
        int4 o4 = make_int4(ex, ex + t0, ex + t1, ex + t2);
        *reinterpret_cast<int4*>(off + idx) = o4;
        *reinterpret_cast<int4*>(cur + idx) = o4;
    } else if (idx < N) {
        off[idx] = ex;           cur[idx] = ex;
        if (idx + 1 < N) { off[idx + 1] = ex + t0; cur[idx + 1] = ex + t0; }
        if (idx + 2 < N) { off[idx + 2] = ex + t1; cur[idx + 2] = ex + t1; }
    }
}

// ---------------------------------------------------------------------------
// Pass 3: scatter edges into destination bins (round-14 form: per-relation
// launches). One packed 8B write per edge.
// ---------------------------------------------------------------------------
__global__ void scatter_kernel(const int* __restrict__ src,
                               const int* __restrict__ dst,
                               const float* __restrict__ val,
                               int nE, int base, int* __restrict__ cur,
                               int2* __restrict__ bpk)
{
    int i = blockIdx.x * blockDim.x + threadIdx.x;
    if (i < nE) {
        int d   = dst[i];
        int pos = atomicAdd(&cur[base + d], 1);
        bpk[pos] = make_int2(src[i], __float_as_int(val[i]));
    }
}

// ---------------------------------------------------------------------------
// Pass 4: gather-accumulate (round-14 form: MLP=2 — latency hiding comes from
// occupancy, NOT per-thread unroll; MLP=4 blew the register file twice now).
// One warp per output row; each lane owns 4 columns (8B per edge).
// fp32 accumulation; items -> fp16 nbh, users -> fp32 u_emb.
// ---------------------------------------------------------------------------
__global__ void __launch_bounds__(256)
gather_kernel(const int* __restrict__ off,
              const int2* __restrict__ bpk,
              const __half2* __restrict__ xh,
              __half2* __restrict__ nbh, float* __restrict__ uemb,
              int n3, int nrows)
{
    int w = (blockIdx.x * blockDim.x + threadIdx.x) >> 5;
    if (w >= nrows) return;
    const int lane = threadIdx.x & 31;

    unsigned long long pol;
    asm("createpolicy.fractional.L2::evict_last.b64 %0, 1.0;" : "=l"(pol));

    int beg = __ldg(off + w);
    int end = __ldg(off + w + 1);

    float4 a0 = make_float4(0.f, 0.f, 0.f, 0.f);
    float4 a1 = make_float4(0.f, 0.f, 0.f, 0.f);

#define XLOADH(D, SRC)                                                         \
    {                                                                          \
        const __half2* xp = xh + (size_t)(SRC) * (D_C / 2) + lane * 2;         \
        asm volatile("ld.global.nc.L2::cache_hint.b64 %0, [%1], %2;"           \
                     : "=l"(D) : "l"(xp), "l"(pol));                           \
    }
#define XFMAH(A, D, V)                                                         \
    {                                                                          \
        unsigned int _lo = (unsigned int)(D);                                  \
        unsigned int _hi = (unsigned int)((D) >> 32);                          \
        float2 _f0 = __half22float2(*reinterpret_cast<__half2*>(&_lo));        \
        float2 _f1 = __half22float2(*reinterpret_cast<__half2*>(&_hi));        \
        A.x = fmaf(_f0.x, V, A.x); A.y = fmaf(_f0.y, V, A.y);                  \
        A.z = fmaf(_f1.x, V, A.z); A.w = fmaf(_f1.y, V, A.w);                  \
    }

    for (int p = beg; p < end; p += 32) {
        int n = min(32, end - p);
        int2 pk = make_int2(0, 0);
        if (lane < n) pk = __ldg(bpk + p + lane);

        int e = 0;
        for (; e + 2 <= n; e += 2) {
            int   s0 = __shfl_sync(0xffffffffu, pk.x, e);
            int   s1 = __shfl_sync(0xffffffffu, pk.x, e + 1);
            float v0 = __int_as_float(__shfl_sync(0xffffffffu, pk.y, e));
            float v1 = __int_as_float(__shfl_sync(0xffffffffu, pk.y, e + 1));
            unsigned long long d0, d1;
            XLOADH(d0, s0); XLOADH(d1, s1);
            XFMAH(a0, d0, v0); XFMAH(a1, d1, v1);
        }
        if (e < n) {
            int   se = __shfl_sync(0xffffffffu, pk.x, e);
            float ve = __int_as_float(__shfl_sync(0xffffffffu, pk.y, e));
            unsigned long long d; XLOADH(d, se); XFMAH(a0, d, ve);
        }
    }
#undef XLOADH
#undef XFMAH

    a0.x += a1.x; a0.y += a1.y; a0.z += a1.z; a0.w += a1.w;

    if (w < n3) {
        __half2 h0 = __floats2half2_rn(a0.x, a0.y);
        __half2 h1 = __floats2half2_rn(a0.z, a0.w);
        unsigned long long dv =
            ((unsigned long long)*reinterpret_cast<unsigned int*>(&h1) << 32) |
            *reinterpret_cast<unsigned int*>(&h0);
        *reinterpret_cast<unsigned long long*>(
            nbh + (size_t)w * (D_C / 2) + lane * 2) = dv;
    } else {
        *reinterpret_cast<float4*>(
            uemb + (size_t)(w - n3) * D_C + lane * 4) = a0;
    }
}

// ---------------------------------------------------------------------------
// Score + combine v4.1 (UNCHANGED — tensor-core matvec, the round-14 winner)
// ---------------------------------------------------------------------------
__device__ __forceinline__ float4 h4_to_f4(unsigned long long d)
{
    unsigned int lo = (unsigned int)d;
    unsigned int hi = (unsigned int)(d >> 32);
    float2 f0 = __half22float2(*reinterpret_cast<__half2*>(&lo));
    float2 f1 = __half22float2(*reinterpret_cast<__half2*>(&hi));
    return make_float4(f0.x, f0.y, f1.x, f1.y);
}

__device__ __forceinline__ float leaky(float h)
{
    return (h >= 0.f) ? h : 0.2f * h;
}

__global__ void __launch_bounds__(256, 2)
score_kernel(const __half2* __restrict__ xh,
             const __half2* __restrict__ nbh,
             const __half2* __restrict__ Ih,   // 3 x 128 x 128 fp16 row-major
             float* __restrict__ out,
             int nrows)
{
    extern __shared__ char smc[];
    char*  I_b  = smc + SM_I;    // pair rows: I_pair[p][n] = (I[2p][n], I[2p+1][n])
    char*  Z_b  = smc + SM_Z;    // Z[r][k] fp16, ZPITCH bytes per row
    float* s2   = reinterpret_cast<float*>(smc + SM_S2);  // [2][64]
    float* s_sh = reinterpret_cast<float*>(smc + SM_S);   // [3][64]

    const int tid  = threadIdx.x;
    const int lane = tid & 31;
    const int wid  = tid >> 5;          // 8 warps
    const int gid  = lane >> 2;         // 0..7
    const int m    = lane & 3;          // 0..3
    const int rt   = wid >> 1;          // row tile 0..3 (16 rows each)
    const int ch   = wid & 1;           // col half 0..1 (64 cols each)
    const int row0 = blockIdx.x * 64;
    const int rows = min(64, nrows - row0);
    const size_t rel_stride = (size_t)nrows * (D_C / 2);  // half2 units

#pragma unroll 1
    for (int rel = 0; rel < 3; rel++) {
        const __half2* nbp  = nbh + (size_t)rel * rel_stride;
        const unsigned int* Ig =
            reinterpret_cast<const unsigned int*>(Ih + (size_t)rel * (D_C * D_C / 2));

        // ---- stage I as k-pair-interleaved half2 rows (ALL 64 n-pairs) -------
        for (int idx = tid; idx < 64 * 64; idx += 256) {
            int p = idx >> 6;          // k-pair row 0..63
            int j = idx & 63;          // n-pair 0..63 (n = 2j, 2j+1)
            unsigned int u0 = Ig[(2 * p)     * 64 + j];
            unsigned int u1 = Ig[(2 * p + 1) * 64 + j];
            __half2 h0 = *reinterpret_cast<__half2*>(&u0);
            __half2 h1 = *reinterpret_cast<__half2*>(&u1);
            __half2 lo = __lows2half2(h0, h1);
            __half2 hi = __highs2half2(h0, h1);
            unsigned long long dv =
                ((unsigned long long)*reinterpret_cast<unsigned int*>(&hi) << 32) |
                *reinterpret_cast<unsigned int*>(&lo);
            *reinterpret_cast<unsigned long long*>(I_b + p * IPITCH + j * 8) = dv;
        }
        // ---- stage Z = xh * nbh (fp16) ---------------------------------------
        for (int idx = tid; idx < 64 * 32; idx += 256) {
            int r = idx >> 5;
            int q = idx & 31;          // 4-half group
            unsigned long long dz = 0ull;
            if (r < rows) {
                size_t offh = (size_t)(row0 + r) * (D_C / 2) + (q << 1);
                unsigned long long dx =
                    *reinterpret_cast<const unsigned long long*>(xh + offh);
                unsigned long long dn =
                    *reinterpret_cast<const unsigned long long*>(nbp + offh);
                unsigned int xl = (unsigned int)dx, xu = (unsigned int)(dx >> 32);
                unsigned int nl = (unsigned int)dn, nu = (unsigned int)(dn >> 32);
                __half2 zl = __hmul2(*reinterpret_cast<__half2*>(&xl),
                                     *reinterpret_cast<__half2*>(&nl));
                __half2 zu = __hmul2(*reinterpret_cast<__half2*>(&xu),
                                     *reinterpret_cast<__half2*>(&nu));
                dz = ((unsigned long long)*reinterpret_cast<unsigned int*>(&zu) << 32) |
                     *reinterpret_cast<unsigned int*>(&zl);
            }
            *reinterpret_cast<unsigned long long*>(Z_b + r * ZPITCH + q * 8) = dz;
        }
        __syncthreads();

        // ---- HMMA: 8 k-steps x 8 n-tiles --------------------------------------
        float acc[8][4];
#pragma unroll
        for (int ct = 0; ct < 8; ct++)
#pragma unroll
            for (int c = 0; c < 4; c++) acc[ct][c] = 0.f;

        const char* za = Z_b + (rt * 16 + gid) * ZPITCH + m * 4;
#pragma unroll
        for (int ks = 0; ks < 8; ks++) {
            const char* zk = za + ks * 32;
            unsigned int fa0 = *reinterpret_cast<const unsigned int*>(zk);
            unsigned int fa1 = *reinterpret_cast<const unsigned int*>(zk + 8 * ZPITCH);
            unsigned int fa2 = *reinterpret_cast<const unsigned int*>(zk + 16);
            unsigned int fa3 = *reinterpret_cast<const unsigned int*>(zk + 8 * ZPITCH + 16);
            const char* ik = I_b + (8 * ks + m) * IPITCH + (ch * 64 + gid) * 4;
#pragma unroll
            for (int ct = 0; ct < 8; ct++) {
                unsigned int fb0 = *reinterpret_cast<const unsigned int*>(ik + ct * 32);
                unsigned int fb1 = *reinterpret_cast<const unsigned int*>(ik + ct * 32 + 4 * IPITCH);
                asm volatile(
                    "mma.sync.aligned.m16n8k16.row.col.f32.f16.f16.f32 "
                    "{%0,%1,%2,%3}, {%4,%5,%6,%7}, {%8,%9}, {%0,%1,%2,%3};"
                    : "+f"(acc[ct][0]), "+f"(acc[ct][1]),
                      "+f"(acc[ct][2]), "+f"(acc[ct][3])
                    : "r"(fa0), "r"(fa1), "r"(fa2), "r"(fa3),
                      "r"(fb0), "r"(fb1));
            }
        }

        // ---- leaky + column-sum + cross-lane reduce ---------------------------
        float rs0 = 0.f, rs1 = 0.f;
#pragma unroll
        for (int ct = 0; ct < 8; ct++) {
            rs0 += leaky(acc[ct][0]) + leaky(acc[ct][1]);   // row rt*16+gid
            rs1 += leaky(acc[ct][2]) + leaky(acc[ct][3]);   // row rt*16+gid+8
        }
        rs0 += __shfl_xor_sync(0xffffffffu, rs0, 1);
        rs0 += __shfl_xor_sync(0xffffffffu, rs0, 2);
        rs1 += __shfl_xor_sync(0xffffffffu, rs1, 1);
        rs1 += __shfl_xor_sync(0xffffffffu, rs1, 2);
        if (m == 0) {
            s2[ch * 64 + rt * 16 + gid]     = rs0;
            s2[ch * 64 + rt * 16 + gid + 8] = rs1;
        }
        __syncthreads();
        if (tid < 64)
            s_sh[rel * 64 + tid] =
                (s2[tid] + s2[64 + tid]) * 0.08838834764831845f;   // 1/sqrt(128)
    }
    __syncthreads();

    // ---- softmax over relations + weighted combine (fp16 nb, fp32 out) -------
    float4* og = reinterpret_cast<float4*>(out);
    for (int idx = tid; idx < 64 * 32; idx += 256) {
        int r  = idx >> 5;
        int c4 = idx & 31;
        if (r >= rows) continue;
        float s0 = s_sh[r];
        float s1 = s_sh[64 + r];
        float s2v = s_sh[128 + r];
        float mx = fmaxf(s0, fmaxf(s1, s2v));
        float e0 = __expf(s0 - mx);
        float e1 = __expf(s1 - mx);
        float e2 = __expf(s2v - mx);
        float inv = 1.f / (e0 + e1 + e2);
        float w0 = e0 * inv, w1 = e1 * inv, w2 = e2 * inv;

        size_t offh = (size_t)(row0 + r) * (D_C / 2) + (c4 << 1);
        float4 av = h4_to_f4(*reinterpret_cast<const unsigned long long*>(nbh + offh));
        float4 bv = h4_to_f4(*reinterpret_cast<const unsigned long long*>(nbh + rel_stride + offh));
        float4 cv = h4_to_f4(*reinterpret_cast<const unsigned long long*>(nbh + 2 * rel_stride + offh));
        float4 o;
        o.x = w0 * av.x + w1 * bv.x + w2 * cv.x;
        o.y = w0 * av.y + w1 * bv.y + w2 * cv.y;
        o.z = w0 * av.z + w1 * bv.z + w2 * cv.z;
        o.w = w0 * av.w + w1 * bv.w + w2 * cv.w;
        og[(size_t)(row0 + r) * 32 + c4] = o;
    }
}

// ---------------------------------------------------------------------------
// Launch
// ---------------------------------------------------------------------------
extern "C" void kernel_launch(void* const* d_in, const int* in_sizes, int n_in,
                              void* d_out, int out_size)
{
    int base = (in_sizes[0] == 1) ? 1 : 0;

    const float* x      = (const float*)d_in[base + 0];
    const int*   srcs[4] = { (const int*)d_in[base + 1], (const int*)d_in[base + 4],
                             (const int*)d_in[base + 7], (const int*)d_in[base + 10] };
    const int*   dsts[4] = { (const int*)d_in[base + 2], (const int*)d_in[base + 5],
                             (const int*)d_in[base + 8], (const int*)d_in[base + 11] };
    const float* vals[4] = { (const float*)d_in[base + 3], (const float*)d_in[base + 6],
                             (const float*)d_in[base + 9], (const float*)d_in[base + 12] };
    const float* I0     = (const float*)d_in[base + 13];
    const float* I1     = (const float*)d_in[base + 14];
    const float* I2     = (const float*)d_in[base + 15];

    int n_items = in_sizes[base + 0] / D_C;
    int nE[4]   = { in_sizes[base + 1], in_sizes[base + 4],
                    in_sizes[base + 7], in_sizes[base + 10] };
    int n_users = out_size / D_C - n_items;
    int n3      = 3 * n_items;
    int nrows   = n3 + n_users;

    float* out_f    = (float*)d_out;
    float* u_emb    = out_f;                          // tuple order: (u_emb, neighbor)
    float* neighbor = out_f + (size_t)n_users * D_C;

    __half2 *nbh, *xh, *Ih; int2 *bpk; int *cnt, *off, *cur, *part;
    cudaGetSymbolAddress((void**)&nbh,  g_nbh);
    cudaGetSymbolAddress((void**)&xh,   g_xh);
    cudaGetSymbolAddress((void**)&Ih,   g_Ih);
    cudaGetSymbolAddress((void**)&bpk,  g_bpk);
    cudaGetSymbolAddress((void**)&cnt,  g_cnt);
    cudaGetSymbolAddress((void**)&off,  g_off);
    cudaGetSymbolAddress((void**)&cur,  g_cur);
    cudaGetSymbolAddress((void**)&part, g_part);

    // --- fp16 copies of x and I (one launch) ------------------------------------
    {
        int n4 = n_items * D_C / 4;
        conv_kernel<<<(n4 + 255) / 256, 256>>>(
            reinterpret_cast<const float4*>(x), n4,
            reinterpret_cast<const float2*>(I0),
            reinterpret_cast<const float2*>(I1),
            reinterpret_cast<const float2*>(I2), xh, Ih);
    }

    // --- build CSR bins ----------------------------------------------------------
    cudaMemsetAsync(cnt, 0, (size_t)nrows * sizeof(int), 0);
    for (int r = 0; r < 4; r++) {
        int b = (r < 3) ? r * n_items : n3;
        int g = ((nE[r] + 3) / 4 + 255) / 256;
        hist_kernel<<<g, 256>>>(dsts[r], nE[r], b, cnt);
    }
    int nparts = (nrows + SCAN_CHUNK - 1) / SCAN_CHUNK;
    block_sum_kernel<<<nparts, 1024>>>(cnt, part, nrows);
    part_scan_kernel<<<1, 1024>>>(part, nparts, off + nrows);
    scan_final_kernel<<<nparts, 1024>>>(cnt, part, off, cur, nrows);
    for (int r = 0; r < 4; r++) {
        int b = (r < 3) ? r * n_items : n3;
        int g = (nE[r] + 255) / 256;
        scatter_kernel<<<g, 256>>>(srcs[r], dsts[r], vals[r], nE[r], b, cur, bpk);
    }

    // --- gather-accumulate (MLP=2; occupancy does the latency hiding) -------------
    {
        int g = ((nrows * 32) + 255) / 256;
        gather_kernel<<<g, 256>>>(off, bpk, xh, nbh, u_emb, n3, nrows);
    }

    // --- score + combine (tensor-core matvec) --------------------------------------
    cudaFuncSetAttribute(score_kernel,
                         cudaFuncAttributeMaxDynamicSharedMemorySize, SM_TOT);
    int nblocks = (n_items + 63) / 64;
    score_kernel<<<nblocks, 256, SM_TOT>>>(xh, nbh, Ih, neighbor, n_items);
}

// round 17
// speedup vs baseline: 1.0603x; 1.0045x over previous
#include <cuda_runtime.h>
#include <cuda_fp16.h>
#include <math.h>

// ---------------------------------------------------------------------------
// Problem constants (fixed by dataset; runtime sizes still read from in_sizes)
// ---------------------------------------------------------------------------
#define D_C       128
#define MAX_ITEMS 200000
#define MAX_USERS 100000
#define MAX_EII   3200000
#define MAX_EUI   1600000
#define MAX_EDGES (3 * MAX_EII + MAX_EUI)          // 11.2M
#define MAX_ROWS  (3 * MAX_ITEMS + MAX_USERS)      // 700K logical output rows
#define SCAN_CHUNK 4096
#define MAX_PARTS ((MAX_ROWS + SCAN_CHUNK - 1) / SCAN_CHUNK + 1)

// smem byte layout for score kernel (padded pitches -> conflict-free frags)
#define IPITCH 544            // 64 pair-rows x (128 half2 = 512B data + 32B pad)
#define ZPITCH 272            // 64 rows x (128 half = 256B data + 16B pad)
#define SM_I   0
#define SM_Z   (64 * IPITCH)                 // 34816
#define SM_S2  (SM_Z + 64 * ZPITCH)          // 52224
#define SM_S   (SM_S2 + 2 * 64 * 4)          // 52736
#define SM_TOT (SM_S + 3 * 64 * 4)           // 53504

// Static device scratch (no allocs allowed).
__device__ __half2 g_nbh [(size_t)3 * MAX_ITEMS * D_C / 2]; // fp16 nb aggregates
__device__ __half2 g_xh  [(size_t)MAX_ITEMS * D_C / 2];     // fp16 copy of x
__device__ __half2 g_Ih  [3 * D_C * D_C / 2];               // fp16 copies of I0..2
__device__ int2    g_bpk [MAX_EDGES];                       // binned (src, val-bits)
__device__ int     g_cnt [MAX_ROWS];
__device__ int     g_off [MAX_ROWS + 1];
__device__ int     g_cur [MAX_ROWS];
__device__ int     g_part[MAX_PARTS];

// ---------------------------------------------------------------------------
// Pass 0: convert x AND the three I matrices to fp16 in one launch.
// ---------------------------------------------------------------------------
__global__ void conv_kernel(const float4* __restrict__ x4, int n4,
                            const float2* __restrict__ I0,
                            const float2* __restrict__ I1,
                            const float2* __restrict__ I2,
                            __half2* __restrict__ xh,
                            __half2* __restrict__ Ih)
{
    int i = blockIdx.x * blockDim.x + threadIdx.x;
    if (i < n4) {
        float4 v = x4[i];
        xh[2 * i]     = __floats2half2_rn(v.x, v.y);
        xh[2 * i + 1] = __floats2half2_rn(v.z, v.w);
    }
    if (i < 3 * D_C * D_C / 2) {
        int rel = i / (D_C * D_C / 2);
        int j   = i % (D_C * D_C / 2);
        const float2* Ip = (rel == 0) ? I0 : (rel == 1) ? I1 : I2;
        float2 v = Ip[j];
        Ih[i] = __floats2half2_rn(v.x, v.y);
    }
}

// ---------------------------------------------------------------------------
// Pass 1: merged histogram — ONE launch, blockIdx.y = relation.
// 4 edges / thread, int4 loads; four relations' atomic streams overlap
// instead of paying 4 ramp-up/drain tails.
// ---------------------------------------------------------------------------
__global__ void hist4_kernel(
    const int* __restrict__ d0, int n0,
    const int* __restrict__ d1, int n1,
    const int* __restrict__ d2, int n2,
    const int* __restrict__ d3, int n3e,
    int ni, int* __restrict__ cnt)
{
    int rel = blockIdx.y;
    const int* dst; int nE; int base;
    if      (rel == 0) { dst = d0; nE = n0;  base = 0;      }
    else if (rel == 1) { dst = d1; nE = n1;  base = ni;     }
    else if (rel == 2) { dst = d2; nE = n2;  base = 2 * ni; }
    else               { dst = d3; nE = n3e; base = 3 * ni; }

    int i0 = (blockIdx.x * blockDim.x + threadIdx.x) * 4;
    if (i0 + 3 < nE) {
        int4 d = *reinterpret_cast<const int4*>(dst + i0);
        atomicAdd(&cnt[base + d.x], 1);
        atomicAdd(&cnt[base + d.y], 1);
        atomicAdd(&cnt[base + d.z], 1);
        atomicAdd(&cnt[base + d.w], 1);
    } else {
        for (int j = i0; j < nE; j++) atomicAdd(&cnt[base + dst[j]], 1);
    }
}

// ---------------------------------------------------------------------------
// Pass 2a/2b/2c: parallel exclusive scan (unchanged)
// ---------------------------------------------------------------------------
__global__ void __launch_bounds__(1024)
block_sum_kernel(const int* __restrict__ cnt, int* __restrict__ part, int N)
{
    __shared__ int ws[32];
    const int tid = threadIdx.x, lane = tid & 31, wid = tid >> 5;
    int idx = blockIdx.x * SCAN_CHUNK + tid * 4;
    int t = 0;
    if (idx + 3 < N) {
        int4 v = *reinterpret_cast<const int4*>(cnt + idx);
        t = v.x + v.y + v.z + v.w;
    } else {
        for (int j = idx; j < min(idx + 4, N); j++) t += cnt[j];
    }
#pragma unroll
    for (int o = 16; o > 0; o >>= 1) t += __shfl_xor_sync(0xffffffffu, t, o);
    if (lane == 0) ws[wid] = t;
    __syncthreads();
    if (wid == 0) {
        int u = ws[lane];
#pragma unroll
        for (int o = 16; o > 0; o >>= 1) u += __shfl_xor_sync(0xffffffffu, u, o);
        if (lane == 0) part[blockIdx.x] = u;
    }
}

__global__ void __launch_bounds__(1024)
part_scan_kernel(int* __restrict__ part, int nparts, int* __restrict__ off_total)
{
    __shared__ int wtot[32];
    const int tid = threadIdx.x, lane = tid & 31, wid = tid >> 5;
    int v = (tid < nparts) ? part[tid] : 0;
    int incl = v;
#pragma unroll
    for (int o = 1; o < 32; o <<= 1) {
        int u = __shfl_up_sync(0xffffffffu, incl, o);
        if (lane >= o) incl += u;
    }
    if (lane == 31) wtot[wid] = incl;
    __syncthreads();
    if (wid == 0) {
        int w = wtot[lane];
        int wi = w;
#pragma unroll
        for (int o = 1; o < 32; o <<= 1) {
            int u = __shfl_up_sync(0xffffffffu, wi, o);
            if (lane >= o) wi += u;
        }
        wtot[lane] = wi - w;
    }
    __syncthreads();
    int excl = wtot[wid] + incl - v;
    if (tid < nparts) part[tid] = excl;
    if (tid == nparts - 1) *off_total = excl + v;
}

__global__ void __launch_bounds__(1024)
scan_final_kernel(const int* __restrict__ cnt, const int* __restrict__ part,
                  int* __restrict__ off, int* __restrict__ cur, int N)
{
    __shared__ int wtot[32];
    __shared__ int wexcl[32];
    const int tid = threadIdx.x, lane = tid & 31, wid = tid >> 5;
    int idx = blockIdx.x * SCAN_CHUNK + tid * 4;

    int4 v = make_int4(0, 0, 0, 0);
    if (idx + 3 < N)      v = *reinterpret_cast<const int4*>(cnt + idx);
    else if (idx < N) {
        v.x = cnt[idx];
        if (idx + 1 < N) v.y = cnt[idx + 1];
        if (idx + 2 < N) v.z = cnt[idx + 2];
    }
    int t0 = v.x, t1 = t0 + v.y, t2 = t1 + v.z, t3 = t2 + v.w;

    int incl = t3;
#pragma unroll
    for (int o = 1; o < 32; o <<= 1) {
        int u = __shfl_up_sync(0xffffffffu, incl, o);
        if (lane >= o) incl += u;
    }
    int thr_excl = incl - t3;
    if (lane == 31) wtot[wid] = incl;
    __syncthreads();
    if (wid == 0) {
        int w = wtot[lane];
        int wi = w;
#pragma unroll
        for (int o = 1; o < 32; o <<= 1) {
            int u = __shfl_up_sync(0xffffffffu, wi, o);
            if (lane >= o) wi += u;
        }
        wexcl[lane] = wi - w;
    }
    __syncthreads();
    int ex = part[blockIdx.x] + wexcl[wid] + thr_excl;
    if (idx + 3 < N) {
        int4 o4 = make_int4(ex, ex + t0, ex + t1, ex + t2);
        *reinterpret_cast<int4*>(off + idx) = o4;
        *reinterpret_cast<int4*>(cur + idx) = o4;
    } else if (idx < N) {
        off[idx] = ex;           cur[idx] = ex;
        if (idx + 1 < N) { off[idx + 1] = ex + t0; cur[idx + 1] = ex + t0; }
        if (idx + 2 < N) { off[idx + 2] = ex + t1; cur[idx + 2] = ex + t1; }
    }
}

// ---------------------------------------------------------------------------
// Pass 3: scatter, 4 edges/thread — int4/float4 sequential loads, then 4
// INDEPENDENT atomic->store chains per thread (latency-chain MLP=4; scalar
// registers only, unlike the gather unroll that blew the RF).
// ---------------------------------------------------------------------------
__global__ void scatter_kernel(const int* __restrict__ src,
                               const int* __restrict__ dst,
                               const float* __restrict__ val,
                               int nE, int base, int* __restrict__ cur,
                               int2* __restrict__ bpk)
{
    int i0 = (blockIdx.x * blockDim.x + threadIdx.x) * 4;
    if (i0 + 3 < nE) {
        int4   s = *reinterpret_cast<const int4*>(src + i0);
        int4   d = *reinterpret_cast<const int4*>(dst + i0);
        float4 v = *reinterpret_cast<const float4*>(val + i0);
        int p0 = atomicAdd(&cur[base + d.x], 1);
        int p1 = atomicAdd(&cur[base + d.y], 1);
        int p2 = atomicAdd(&cur[base + d.z], 1);
        int p3 = atomicAdd(&cur[base + d.w], 1);
        bpk[p0] = make_int2(s.x, __float_as_int(v.x));
        bpk[p1] = make_int2(s.y, __float_as_int(v.y));
        bpk[p2] = make_int2(s.z, __float_as_int(v.z));
        bpk[p3] = make_int2(s.w, __float_as_int(v.w));
    } else {
        for (int j = i0; j < nE; j++) {
            int pos = atomicAdd(&cur[base + dst[j]], 1);
            bpk[pos] = make_int2(src[j], __float_as_int(val[j]));
        }
    }
}

// ---------------------------------------------------------------------------
// Pass 4: gather-accumulate (UNCHANGED: MLP=2, lean registers — occupancy
// does the latency hiding). One warp per output row; 8B per edge per lane.
// fp32 accumulation; items -> fp16 nbh, users -> fp32 u_emb.
// ---------------------------------------------------------------------------
__global__ void __launch_bounds__(256)
gather_kernel(const int* __restrict__ off,
              const int2* __restrict__ bpk,
              const __half2* __restrict__ xh,
              __half2* __restrict__ nbh, float* __restrict__ uemb,
              int n3, int nrows)
{
    int w = (blockIdx.x * blockDim.x + threadIdx.x) >> 5;
    if (w >= nrows) return;
    const int lane = threadIdx.x & 31;

    unsigned long long pol;
    asm("createpolicy.fractional.L2::evict_last.b64 %0, 1.0;" : "=l"(pol));

    int beg = __ldg(off + w);
    int end = __ldg(off + w + 1);

    float4 a0 = make_float4(0.f, 0.f, 0.f, 0.f);
    float4 a1 = make_float4(0.f, 0.f, 0.f, 0.f);

#define XLOADH(D, SRC)                                                         \
    {                                                                          \
        const __half2* xp = xh + (size_t)(SRC) * (D_C / 2) + lane * 2;         \
        asm volatile("ld.global.nc.L2::cache_hint.b64 %0, [%1], %2;"           \
                     : "=l"(D) : "l"(xp), "l"(pol));                           \
    }
#define XFMAH(A, D, V)                                                         \
    {                                                                          \
        unsigned int _lo = (unsigned int)(D);                                  \
        unsigned int _hi = (unsigned int)((D) >> 32);                          \
        float2 _f0 = __half22float2(*reinterpret_cast<__half2*>(&_lo));        \
        float2 _f1 = __half22float2(*reinterpret_cast<__half2*>(&_hi));        \
        A.x = fmaf(_f0.x, V, A.x); A.y = fmaf(_f0.y, V, A.y);                  \
        A.z = fmaf(_f1.x, V, A.z); A.w = fmaf(_f1.y, V, A.w);                  \
    }

    for (int p = beg; p < end; p += 32) {
        int n = min(32, end - p);
        int2 pk = make_int2(0, 0);
        if (lane < n) pk = __ldg(bpk + p + lane);

        int e = 0;
        for (; e + 2 <= n; e += 2) {
            int   s0 = __shfl_sync(0xffffffffu, pk.x, e);
            int   s1 = __shfl_sync(0xffffffffu, pk.x, e + 1);
            float v0 = __int_as_float(__shfl_sync(0xffffffffu, pk.y, e));
            float v1 = __int_as_float(__shfl_sync(0xffffffffu, pk.y, e + 1));
            unsigned long long d0, d1;
            XLOADH(d0, s0); XLOADH(d1, s1);
            XFMAH(a0, d0, v0); XFMAH(a1, d1, v1);
        }
        if (e < n) {
            int   se = __shfl_sync(0xffffffffu, pk.x, e);
            float ve = __int_as_float(__shfl_sync(0xffffffffu, pk.y, e));
            unsigned long long d; XLOADH(d, se); XFMAH(a0, d, ve);
        }
    }
#undef XLOADH
#undef XFMAH

    a0.x += a1.x; a0.y += a1.y; a0.z += a1.z; a0.w += a1.w;

    if (w < n3) {
        __half2 h0 = __floats2half2_rn(a0.x, a0.y);
        __half2 h1 = __floats2half2_rn(a0.z, a0.w);
        unsigned long long dv =
            ((unsigned long long)*reinterpret_cast<unsigned int*>(&h1) << 32) |
            *reinterpret_cast<unsigned int*>(&h0);
        *reinterpret_cast<unsigned long long*>(
            nbh + (size_t)w * (D_C / 2) + lane * 2) = dv;
    } else {
        *reinterpret_cast<float4*>(
            uemb + (size_t)(w - n3) * D_C + lane * 4) = a0;
    }
}

// ---------------------------------------------------------------------------
// Score + combine v4.1 (UNCHANGED — tensor-core matvec, the round-14 winner)
// ---------------------------------------------------------------------------
__device__ __forceinline__ float4 h4_to_f4(unsigned long long d)
{
    unsigned int lo = (unsigned int)d;
    unsigned int hi = (unsigned int)(d >> 32);
    float2 f0 = __half22float2(*reinterpret_cast<__half2*>(&lo));
    float2 f1 = __half22float2(*reinterpret_cast<__half2*>(&hi));
    return make_float4(f0.x, f0.y, f1.x, f1.y);
}

__device__ __forceinline__ float leaky(float h)
{
    return (h >= 0.f) ? h : 0.2f * h;
}

__global__ void __launch_bounds__(256, 2)
score_kernel(const __half2* __restrict__ xh,
             const __half2* __restrict__ nbh,
             const __half2* __restrict__ Ih,   // 3 x 128 x 128 fp16 row-major
             float* __restrict__ out,
             int nrows)
{
    extern __shared__ char smc[];
    char*  I_b  = smc + SM_I;    // pair rows: I_pair[p][n] = (I[2p][n], I[2p+1][n])
    char*  Z_b  = smc + SM_Z;    // Z[r][k] fp16, ZPITCH bytes per row
    float* s2   = reinterpret_cast<float*>(smc + SM_S2);  // [2][64]
    float* s_sh = reinterpret_cast<float*>(smc + SM_S);   // [3][64]

    const int tid  = threadIdx.x;
    const int lane = tid & 31;
    const int wid  = tid >> 5;          // 8 warps
    const int gid  = lane >> 2;         // 0..7
    const int m    = lane & 3;          // 0..3
    const int rt   = wid >> 1;          // row tile 0..3 (16 rows each)
    const int ch   = wid & 1;           // col half 0..1 (64 cols each)
    const int row0 = blockIdx.x * 64;
    const int rows = min(64, nrows - row0);
    const size_t rel_stride = (size_t)nrows * (D_C / 2);  // half2 units

#pragma unroll 1
    for (int rel = 0; rel < 3; rel++) {
        const __half2* nbp  = nbh + (size_t)rel * rel_stride;
        const unsigned int* Ig =
            reinterpret_cast<const unsigned int*>(Ih + (size_t)rel * (D_C * D_C / 2));

        // ---- stage I as k-pair-interleaved half2 rows (ALL 64 n-pairs) -------
        for (int idx = tid; idx < 64 * 64; idx += 256) {
            int p = idx >> 6;          // k-pair row 0..63
            int j = idx & 63;          // n-pair 0..63 (n = 2j, 2j+1)
            unsigned int u0 = Ig[(2 * p)     * 64 + j];
            unsigned int u1 = Ig[(2 * p + 1) * 64 + j];
            __half2 h0 = *reinterpret_cast<__half2*>(&u0);
            __half2 h1 = *reinterpret_cast<__half2*>(&u1);
            __half2 lo = __lows2half2(h0, h1);
            __half2 hi = __highs2half2(h0, h1);
            unsigned long long dv =
                ((unsigned long long)*reinterpret_cast<unsigned int*>(&hi) << 32) |
                *reinterpret_cast<unsigned int*>(&lo);
            *reinterpret_cast<unsigned long long*>(I_b + p * IPITCH + j * 8) = dv;
        }
        // ---- stage Z = xh * nbh (fp16) ---------------------------------------
        for (int idx = tid; idx < 64 * 32; idx += 256) {
            int r = idx >> 5;
            int q = idx & 31;          // 4-half group
            unsigned long long dz = 0ull;
            if (r < rows) {
                size_t offh = (size_t)(row0 + r) * (D_C / 2) + (q << 1);
                unsigned long long dx =
                    *reinterpret_cast<const unsigned long long*>(xh + offh);
                unsigned long long dn =
                    *reinterpret_cast<const unsigned long long*>(nbp + offh);
                unsigned int xl = (unsigned int)dx, xu = (unsigned int)(dx >> 32);
                unsigned int nl = (unsigned int)dn, nu = (unsigned int)(dn >> 32);
                __half2 zl = __hmul2(*reinterpret_cast<__half2*>(&xl),
                                     *reinterpret_cast<__half2*>(&nl));
                __half2 zu = __hmul2(*reinterpret_cast<__half2*>(&xu),
                                     *reinterpret_cast<__half2*>(&nu));
                dz = ((unsigned long long)*reinterpret_cast<unsigned int*>(&zu) << 32) |
                     *reinterpret_cast<unsigned int*>(&zl);
            }
            *reinterpret_cast<unsigned long long*>(Z_b + r * ZPITCH + q * 8) = dz;
        }
        __syncthreads();

        // ---- HMMA: 8 k-steps x 8 n-tiles --------------------------------------
        float acc[8][4];
#pragma unroll
        for (int ct = 0; ct < 8; ct++)
#pragma unroll
            for (int c = 0; c < 4; c++) acc[ct][c] = 0.f;

        const char* za = Z_b + (rt * 16 + gid) * ZPITCH + m * 4;
#pragma unroll
        for (int ks = 0; ks < 8; ks++) {
            const char* zk = za + ks * 32;
            unsigned int fa0 = *reinterpret_cast<const unsigned int*>(zk);
            unsigned int fa1 = *reinterpret_cast<const unsigned int*>(zk + 8 * ZPITCH);
            unsigned int fa2 = *reinterpret_cast<const unsigned int*>(zk + 16);
            unsigned int fa3 = *reinterpret_cast<const unsigned int*>(zk + 8 * ZPITCH + 16);
            const char* ik = I_b + (8 * ks + m) * IPITCH + (ch * 64 + gid) * 4;
#pragma unroll
            for (int ct = 0; ct < 8; ct++) {
                unsigned int fb0 = *reinterpret_cast<const unsigned int*>(ik + ct * 32);
                unsigned int fb1 = *reinterpret_cast<const unsigned int*>(ik + ct * 32 + 4 * IPITCH);
                asm volatile(
                    "mma.sync.aligned.m16n8k16.row.col.f32.f16.f16.f32 "
                    "{%0,%1,%2,%3}, {%4,%5,%6,%7}, {%8,%9}, {%0,%1,%2,%3};"
                    : "+f"(acc[ct][0]), "+f"(acc[ct][1]),
                      "+f"(acc[ct][2]), "+f"(acc[ct][3])
                    : "r"(fa0), "r"(fa1), "r"(fa2), "r"(fa3),
                      "r"(fb0), "r"(fb1));
            }
        }

        // ---- leaky + column-sum + cross-lane reduce ---------------------------
        float rs0 = 0.f, rs1 = 0.f;
#pragma unroll
        for (int ct = 0; ct < 8; ct++) {
            rs0 += leaky(acc[ct][0]) + leaky(acc[ct][1]);   // row rt*16+gid
            rs1 += leaky(acc[ct][2]) + leaky(acc[ct][3]);   // row rt*16+gid+8
        }
        rs0 += __shfl_xor_sync(0xffffffffu, rs0, 1);
        rs0 += __shfl_xor_sync(0xffffffffu, rs0, 2);
        rs1 += __shfl_xor_sync(0xffffffffu, rs1, 1);
        rs1 += __shfl_xor_sync(0xffffffffu, rs1, 2);
        if (m == 0) {
            s2[ch * 64 + rt * 16 + gid]     = rs0;
            s2[ch * 64 + rt * 16 + gid + 8] = rs1;
        }
        __syncthreads();
        if (tid < 64)
            s_sh[rel * 64 + tid] =
                (s2[tid] + s2[64 + tid]) * 0.08838834764831845f;   // 1/sqrt(128)
    }
    __syncthreads();

    // ---- softmax over relations + weighted combine (fp16 nb, fp32 out) -------
    float4* og = reinterpret_cast<float4*>(out);
    for (int idx = tid; idx < 64 * 32; idx += 256) {
        int r  = idx >> 5;
        int c4 = idx & 31;
        if (r >= rows) continue;
        float s0 = s_sh[r];
        float s1 = s_sh[64 + r];
        float s2v = s_sh[128 + r];
        float mx = fmaxf(s0, fmaxf(s1, s2v));
        float e0 = __expf(s0 - mx);
        float e1 = __expf(s1 - mx);
        float e2 = __expf(s2v - mx);
        float inv = 1.f / (e0 + e1 + e2);
        float w0 = e0 * inv, w1 = e1 * inv, w2 = e2 * inv;

        size_t offh = (size_t)(row0 + r) * (D_C / 2) + (c4 << 1);
        float4 av = h4_to_f4(*reinterpret_cast<const unsigned long long*>(nbh + offh));
        float4 bv = h4_to_f4(*reinterpret_cast<const unsigned long long*>(nbh + rel_stride + offh));
        float4 cv = h4_to_f4(*reinterpret_cast<const unsigned long long*>(nbh + 2 * rel_stride + offh));
        float4 o;
        o.x = w0 * av.x + w1 * bv.x + w2 * cv.x;
        o.y = w0 * av.y + w1 * bv.y + w2 * cv.y;
        o.z = w0 * av.z + w1 * bv.z + w2 * cv.z;
        o.w = w0 * av.w + w1 * bv.w + w2 * cv.w;
        og[(size_t)(row0 + r) * 32 + c4] = o;
    }
}

// ---------------------------------------------------------------------------
// Launch
// ---------------------------------------------------------------------------
extern "C" void kernel_launch(void* const* d_in, const int* in_sizes, int n_in,
                              void* d_out, int out_size)
{
    int base = (in_sizes[0] == 1) ? 1 : 0;

    const float* x      = (const float*)d_in[base + 0];
    const int*   srcs[4] = { (const int*)d_in[base + 1], (const int*)d_in[base + 4],
                             (const int*)d_in[base + 7], (const int*)d_in[base + 10] };
    const int*   dsts[4] = { (const int*)d_in[base + 2], (const int*)d_in[base + 5],
                             (const int*)d_in[base + 8], (const int*)d_in[base + 11] };
    const float* vals[4] = { (const float*)d_in[base + 3], (const float*)d_in[base + 6],
                             (const float*)d_in[base + 9], (const float*)d_in[base + 12] };
    const float* I0     = (const float*)d_in[base + 13];
    const float* I1     = (const float*)d_in[base + 14];
    const float* I2     = (const float*)d_in[base + 15];

    int n_items = in_sizes[base + 0] / D_C;
    int nE[4]   = { in_sizes[base + 1], in_sizes[base + 4],
                    in_sizes[base + 7], in_sizes[base + 10] };
    int n_users = out_size / D_C - n_items;
    int n3      = 3 * n_items;
    int nrows   = n3 + n_users;

    float* out_f    = (float*)d_out;
    float* u_emb    = out_f;                          // tuple order: (u_emb, neighbor)
    float* neighbor = out_f + (size_t)n_users * D_C;

    __half2 *nbh, *xh, *Ih; int2 *bpk; int *cnt, *off, *cur, *part;
    cudaGetSymbolAddress((void**)&nbh,  g_nbh);
    cudaGetSymbolAddress((void**)&xh,   g_xh);
    cudaGetSymbolAddress((void**)&Ih,   g_Ih);
    cudaGetSymbolAddress((void**)&bpk,  g_bpk);
    cudaGetSymbolAddress((void**)&cnt,  g_cnt);
    cudaGetSymbolAddress((void**)&off,  g_off);
    cudaGetSymbolAddress((void**)&cur,  g_cur);
    cudaGetSymbolAddress((void**)&part, g_part);

    // --- fp16 copies of x and I (one launch) ------------------------------------
    {
        int n4 = n_items * D_C / 4;
        conv_kernel<<<(n4 + 255) / 256, 256>>>(
            reinterpret_cast<const float4*>(x), n4,
            reinterpret_cast<const float2*>(I0),
            reinterpret_cast<const float2*>(I1),
            reinterpret_cast<const float2*>(I2), xh, Ih);
    }

    // --- build CSR bins ----------------------------------------------------------
    cudaMemsetAsync(cnt, 0, (size_t)nrows * sizeof(int), 0);
    {
        int maxE = max(max(nE[0], nE[1]), max(nE[2], nE[3]));
        dim3 grid(((maxE + 3) / 4 + 255) / 256, 4);
        hist4_kernel<<<grid, 256>>>(dsts[0], nE[0], dsts[1], nE[1],
                                    dsts[2], nE[2], dsts[3], nE[3],
                                    n_items, cnt);
    }
    int nparts = (nrows + SCAN_CHUNK - 1) / SCAN_CHUNK;
    block_sum_kernel<<<nparts, 1024>>>(cnt, part, nrows);
    part_scan_kernel<<<1, 1024>>>(part, nparts, off + nrows);
    scan_final_kernel<<<nparts, 1024>>>(cnt, part, off, cur, nrows);
    for (int r = 0; r < 4; r++) {
        int b = (r < 3) ? r * n_items : n3;
        int g = ((nE[r] + 3) / 4 + 255) / 256;
        scatter_kernel<<<g, 256>>>(srcs[r], dsts[r], vals[r], nE[r], b, cur, bpk);
    }

    // --- gather-accumulate (MLP=2; occupancy does the latency hiding) -------------
    {
        int g = ((nrows * 32) + 255) / 256;
        gather_kernel<<<g, 256>>>(off, bpk, xh, nbh, u_emb, n3, nrows);
    }

    // --- score + combine (tensor-core matvec) --------------------------------------
    cudaFuncSetAttribute(score_kernel,
                         cudaFuncAttributeMaxDynamicSharedMemorySize, SM_TOT);
    int nblocks = (n_items + 63) / 64;
    score_kernel<<<nblocks, 256, SM_TOT>>>(xh, nbh, Ih, neighbor, n_items);
}